// round 3
// baseline (speedup 1.0000x reference)
#include <cuda_runtime.h>
#include <math.h>

#define CCH    1024
#define HW     49
#define HW2    2401
#define CH     128            // channels per smem chunk
#define NCHUNK 8
#define NGROUP 4
#define CPG    32             // channels per group per chunk
#define NTHR   224            // 7 warps: 4x56 (phase1), 32x7 (phase3)
#define PADW   56             // padded row: 7 groups of 8 floats (q/k/att)
#define VROW   52             // padded row for v in phase 3 (i-contiguous)

// smem layout (floats)
#define QS_OFF   0
#define KS_OFF   (CH*PADW)                  // 7168
#define PART_OFF (2*CH*PADW)                // 14336
#define ATT_OFF  (PART_OFF + NGROUP*HW2)    // 23940
#define RED_OFF  (ATT_OFF + HW*PADW)        // 26684
#define SM_FLOATS (RED_OFF + 8)             // 26692 floats = 106768 B

__global__ __launch_bounds__(NTHR, 2)
void pam_kernel(const float* __restrict__ vin,
                const float* __restrict__ qin,
                const float* __restrict__ kin,
                float* __restrict__ out)
{
    extern __shared__ float smem[];
    float* q_s   = smem + QS_OFF;     // phase1 q chunk / phase3 v chunk (as VROW rows)
    float* k_s   = smem + KS_OFF;     // phase1 k chunk
    float* part  = smem + PART_OFF;   // phase1 partials / phase3 o_s staging
    float* att_p = smem + ATT_OFF;    // padded attention [49][56]
    float* red   = smem + RED_OFF;

    const int b = blockIdx.x;
    const int t = threadIdx.x;

    const float* qb = qin + (size_t)b * CCH * HW;
    const float* kb = kin + (size_t)b * CCH * HW;
    const float* vb = vin + (size_t)b * CCH * HW;
    float*       ob = out + (size_t)b * CCH * HW;

    // ================= Phase 1: logits = q^T k =================
    const int g    = t / 56;          // 0..3
    const int slot = t - g * 56;      // 0..55, active < 49
    const int ti   = slot / 7;
    const int tj   = slot - ti * 7;
    const bool active = (slot < 49);

    float acc[49];
#pragma unroll
    for (int p = 0; p < 49; ++p) acc[p] = 0.f;

    for (int ch = 0; ch < NCHUNK; ++ch) {
        // load 128-channel chunk of q,k -> padded smem rows (7 groups of 8)
        const float4* qg4 = (const float4*)(qb + ch * CH * HW);
        const float4* kg4 = (const float4*)(kb + ch * CH * HW);
#pragma unroll
        for (int it = 0; it < 7; ++it) {           // 1568 float4 = 7*224
            int idx4 = t + it * NTHR;
            float4 qa = qg4[idx4];
            float4 ka = kg4[idx4];
            int f   = idx4 * 4;
            int row = f / 49;
            int pos = f - row * 49;
            int pg  = pos / 7;
            int pr  = pos - pg * 7;
            float qe[4] = {qa.x, qa.y, qa.z, qa.w};
            float ke[4] = {ka.x, ka.y, ka.z, ka.w};
#pragma unroll
            for (int u = 0; u < 4; ++u) {
                int off = row * PADW + pg * 8 + pr;
                q_s[off] = qe[u];
                k_s[off] = ke[u];
                if (++pr == 7) { pr = 0; if (++pg == 7) { pg = 0; ++row; } }
            }
        }
        __syncthreads();

        if (active) {
            const float* qp = q_s + g * CPG * PADW + ti * 8;
            const float* kp = k_s + g * CPG * PADW + tj * 8;
#pragma unroll 2
            for (int cc = 0; cc < CPG; ++cc) {
                float4 qa = *(const float4*)(qp);
                float4 qb4 = *(const float4*)(qp + 4);
                float4 ka = *(const float4*)(kp);
                float4 kb4 = *(const float4*)(kp + 4);
                float qv[7] = {qa.x, qa.y, qa.z, qa.w, qb4.x, qb4.y, qb4.z};
                float kv[7] = {ka.x, ka.y, ka.z, ka.w, kb4.x, kb4.y, kb4.z};
#pragma unroll
                for (int a = 0; a < 7; ++a)
#pragma unroll
                    for (int j = 0; j < 7; ++j)
                        acc[a * 7 + j] += qv[a] * kv[j];
                qp += PADW;
                kp += PADW;
            }
        }
        __syncthreads();
    }

    if (active) {
#pragma unroll
        for (int a = 0; a < 7; ++a)
#pragma unroll
            for (int j = 0; j < 7; ++j)
                part[g * HW2 + (ti * 7 + a) * HW + (tj * 7 + j)] = acc[a * 7 + j];
    }
    __syncthreads();

    // ================= Phase 2: flat softmax over 2401 =========
    float lmax = -INFINITY;
    for (int p = t; p < HW2; p += NTHR) {
        float s = part[p] + part[HW2 + p] + part[2 * HW2 + p] + part[3 * HW2 + p];
        int i = p / 49, j = p - i * 49;
        int jg = j / 7, jr = j - jg * 7;
        att_p[i * PADW + jg * 8 + jr] = s;
        lmax = fmaxf(lmax, s);
    }
#pragma unroll
    for (int o = 16; o > 0; o >>= 1)
        lmax = fmaxf(lmax, __shfl_xor_sync(0xFFFFFFFFu, lmax, o));
    if ((t & 31) == 0) red[t >> 5] = lmax;
    __syncthreads();
    float bmax = red[0];
#pragma unroll
    for (int w = 1; w < 7; ++w) bmax = fmaxf(bmax, red[w]);

    float lsum = 0.f;
    for (int p = t; p < HW2; p += NTHR) {
        int i = p / 49, j = p - i * 49;
        int jg = j / 7, jr = j - jg * 7;
        int pp = i * PADW + jg * 8 + jr;
        float e = __expf(att_p[pp] - bmax);
        att_p[pp] = e;
        lsum += e;
    }
    __syncthreads();   // all reads of red (max) done
#pragma unroll
    for (int o = 16; o > 0; o >>= 1)
        lsum += __shfl_xor_sync(0xFFFFFFFFu, lsum, o);
    if ((t & 31) == 0) red[t >> 5] = lsum;
    __syncthreads();
    float bsum = red[0];
#pragma unroll
    for (int w = 1; w < 7; ++w) bsum += red[w];
    const float inv = 1.f / bsum;
    for (int p = t; p < HW * PADW; p += NTHR) att_p[p] *= inv;  // pads harmless

    // ================= Phase 3: out = v @ att + v ==============
    float* v_s = q_s;     // [128][VROW], i-contiguous
    float* o_s = part;    // [128][49] compact staging

    const int jt = t % 7;         // 0..6, all active
    const int ct = t / 7;         // 0..31 -> 4 channel rows
    const int c4 = ct * 4;

    for (int pass = 0; pass < CCH / CH; ++pass) {
        // load v chunk -> v_s padded rows of 52
        const float4* vg4 = (const float4*)(vb + pass * CH * HW);
#pragma unroll
        for (int it = 0; it < 7; ++it) {
            int idx4 = t + it * NTHR;
            float4 va = vg4[idx4];
            int f   = idx4 * 4;
            int row = f / 49;
            int pos = f - row * 49;
            float ve[4] = {va.x, va.y, va.z, va.w};
#pragma unroll
            for (int u = 0; u < 4; ++u) {
                v_s[row * VROW + pos] = ve[u];
                if (++pos == 49) { pos = 0; ++row; }
            }
        }
        __syncthreads();   // A: v_s ready; (pass0) att_p ready; prev o_s drained

        float oacc[28];
#pragma unroll
        for (int p = 0; p < 28; ++p) oacc[p] = 0.f;

        const float* ap = att_p + jt * 8;
#pragma unroll 2
        for (int i4 = 0; i4 < 12; ++i4) {
            float4 vv0 = *(const float4*)(v_s + (c4 + 0) * VROW + i4 * 4);
            float4 vv1 = *(const float4*)(v_s + (c4 + 1) * VROW + i4 * 4);
            float4 vv2 = *(const float4*)(v_s + (c4 + 2) * VROW + i4 * 4);
            float4 vv3 = *(const float4*)(v_s + (c4 + 3) * VROW + i4 * 4);
#pragma unroll
            for (int u = 0; u < 4; ++u) {
                int i = i4 * 4 + u;
                float4 aa = *(const float4*)(ap + i * PADW);
                float4 ab = *(const float4*)(ap + i * PADW + 4);
                float av[7] = {aa.x, aa.y, aa.z, aa.w, ab.x, ab.y, ab.z};
                float w0 = (u == 0) ? vv0.x : (u == 1) ? vv0.y : (u == 2) ? vv0.z : vv0.w;
                float w1 = (u == 0) ? vv1.x : (u == 1) ? vv1.y : (u == 2) ? vv1.z : vv1.w;
                float w2 = (u == 0) ? vv2.x : (u == 1) ? vv2.y : (u == 2) ? vv2.z : vv2.w;
                float w3 = (u == 0) ? vv3.x : (u == 1) ? vv3.y : (u == 2) ? vv3.z : vv3.w;
#pragma unroll
                for (int j = 0; j < 7; ++j) {
                    oacc[0 * 7 + j] += w0 * av[j];
                    oacc[1 * 7 + j] += w1 * av[j];
                    oacc[2 * 7 + j] += w2 * av[j];
                    oacc[3 * 7 + j] += w3 * av[j];
                }
            }
        }
        {   // remainder i = 48
            const int i = 48;
            float4 aa = *(const float4*)(ap + i * PADW);
            float4 ab = *(const float4*)(ap + i * PADW + 4);
            float av[7] = {aa.x, aa.y, aa.z, aa.w, ab.x, ab.y, ab.z};
            float w0 = v_s[(c4 + 0) * VROW + i];
            float w1 = v_s[(c4 + 1) * VROW + i];
            float w2 = v_s[(c4 + 2) * VROW + i];
            float w3 = v_s[(c4 + 3) * VROW + i];
#pragma unroll
            for (int j = 0; j < 7; ++j) {
                oacc[0 * 7 + j] += w0 * av[j];
                oacc[1 * 7 + j] += w1 * av[j];
                oacc[2 * 7 + j] += w2 * av[j];
                oacc[3 * 7 + j] += w3 * av[j];
            }
        }

        // epilogue: residual add, stage compact
#pragma unroll
        for (int r = 0; r < 4; ++r) {
            int c = c4 + r;
#pragma unroll
            for (int j = 0; j < 7; ++j) {
                int col = jt * 7 + j;
                o_s[c * HW + col] = oacc[r * 7 + j] + v_s[c * VROW + col];
            }
        }
        __syncthreads();   // B: o_s complete

        float4* od4 = (float4*)(ob + pass * CH * HW);
        const float4* os4 = (const float4*)o_s;
#pragma unroll
        for (int it = 0; it < 7; ++it) {
            int idx4 = t + it * NTHR;
            od4[idx4] = os4[idx4];
        }
        // no sync needed: next loader writes v_s (disjoint from o_s);
        // sync A next pass orders o_s reuse
    }
}

extern "C" void kernel_launch(void* const* d_in, const int* in_sizes, int n_in,
                              void* d_out, int out_size)
{
    const float* v = (const float*)d_in[0];   // v1
    const float* q = (const float*)d_in[1];   // q1
    const float* k = (const float*)d_in[2];   // k1
    float* out = (float*)d_out;

    const int B = in_sizes[0] / (CCH * HW);
    const size_t smem_bytes = SM_FLOATS * sizeof(float);

    cudaFuncSetAttribute(pam_kernel,
                         cudaFuncAttributeMaxDynamicSharedMemorySize,
                         (int)smem_bytes);
    pam_kernel<<<B, NTHR, smem_bytes>>>(v, q, k, out);
}

// round 4
// speedup vs baseline: 1.4314x; 1.4314x over previous
#include <cuda_runtime.h>
#include <math.h>

#define CCH    1024
#define HW     49
#define HW2    2401
#define CH1    64             // phase-1 channels per chunk (double buffered)
#define NCH1   16
#define NGROUP 4
#define CPG    16             // channels per group per chunk
#define CH3    128            // phase-3 channels per pass (double buffered)
#define NCH3   8
#define NTHR   256

// smem (floats):
//  buf  [12544] : ph1: stage s at s*6272 (q at +0, k at +3136)
//                 ph3: v stage s at s*6272
//  part [9604]  : ph1 partial logits / ph3 o_s staging (6272 used)
//  att  [2401]
//  red  [8]
#define PART_OFF 12544
#define ATT_OFF  (PART_OFF + NGROUP*HW2)   // 22148
#define RED_OFF  (ATT_OFF + HW2)           // 24549
#define SM_FLOATS (RED_OFF + 8)            // 24557 floats = 98228 B

__device__ __forceinline__ void cpa16(unsigned dst, const float4* src) {
    asm volatile("cp.async.cg.shared.global [%0], [%1], 16;" :: "r"(dst), "l"(src));
}
#define CP_COMMIT() asm volatile("cp.async.commit_group;")
#define CP_WAIT1()  asm volatile("cp.async.wait_group 1;")
#define CP_WAIT0()  asm volatile("cp.async.wait_group 0;")

__global__ __launch_bounds__(NTHR, 2)
void pam_kernel(const float* __restrict__ vin,
                const float* __restrict__ qin,
                const float* __restrict__ kin,
                float* __restrict__ out)
{
    extern __shared__ float smem[];
    float* part = smem + PART_OFF;
    float* att  = smem + ATT_OFF;
    float* red  = smem + RED_OFF;
    const unsigned smem_u = (unsigned)__cvta_generic_to_shared(smem);

    const int b = blockIdx.x;
    const int t = threadIdx.x;

    const float* qb = qin + (size_t)b * CCH * HW;
    const float* kb = kin + (size_t)b * CCH * HW;
    const float* vb = vin + (size_t)b * CCH * HW;
    float*       ob = out + (size_t)b * CCH * HW;

    // ============ Phase 1: logits = q^T k (double-buffered) ============
    const int g    = t >> 6;          // 0..3
    const int slot = t & 63;          // active < 49
    const int ti   = slot / 7;
    const int tj   = slot - ti * 7;
    const bool active = (slot < 49);

    float acc[49];
#pragma unroll
    for (int p = 0; p < 49; ++p) acc[p] = 0.f;

    // loader: 784 float4 per tensor per chunk
    auto load_qk = [&](int ch, int stage) {
        const float4* q4 = (const float4*)(qb + ch * CH1 * HW);
        const float4* k4 = (const float4*)(kb + ch * CH1 * HW);
        unsigned qs = smem_u + (unsigned)(stage * 2 * CH1 * HW) * 4u;
        unsigned ks = qs + (unsigned)(CH1 * HW) * 4u;
#pragma unroll
        for (int it = 0; it < 4; ++it) {
            int idx = t + it * NTHR;
            if (idx < (CH1 * HW) / 4 + 4) {            // 784; last iter partial
                if (idx < 784) {
                    cpa16(qs + idx * 16u, q4 + idx);
                    cpa16(ks + idx * 16u, k4 + idx);
                }
            }
        }
    };

    load_qk(0, 0);
    CP_COMMIT();

    for (int ch = 0; ch < NCH1; ++ch) {
        const int s = ch & 1;
        if (ch + 1 < NCH1) {
            load_qk(ch + 1, s ^ 1);
            CP_COMMIT();
            CP_WAIT1();
        } else {
            CP_WAIT0();
        }
        __syncthreads();              // chunk ch visible to all

        if (active) {
            const float* qp = smem + s * 2 * CH1 * HW + g * CPG * HW + ti * 7;
            const float* kp = smem + s * 2 * CH1 * HW + CH1 * HW + g * CPG * HW + tj * 7;
#pragma unroll 2
            for (int cc = 0; cc < CPG; ++cc) {
                float qv[7], kv[7];
#pragma unroll
                for (int u = 0; u < 7; ++u) qv[u] = qp[u];
#pragma unroll
                for (int u = 0; u < 7; ++u) kv[u] = kp[u];
#pragma unroll
                for (int a = 0; a < 7; ++a)
#pragma unroll
                    for (int j = 0; j < 7; ++j)
                        acc[a * 7 + j] += qv[a] * kv[j];
                qp += HW;
                kp += HW;
            }
        }
        __syncthreads();              // compute(ch) done before stage reuse
    }

    if (active) {
#pragma unroll
        for (int a = 0; a < 7; ++a)
#pragma unroll
            for (int j = 0; j < 7; ++j)
                part[g * HW2 + (ti * 7 + a) * HW + (tj * 7 + j)] = acc[a * 7 + j];
    }

    // prefetch first v chunk for phase 3 — overlaps entire softmax.
    // buf stage0 last read = chunk-14 compute, already barriered.
    {
        const float4* v4 = (const float4*)vb;
        unsigned vs = smem_u;
#pragma unroll
        for (int it = 0; it < 7; ++it) {
            int idx = t + it * NTHR;
            if (idx < (CH3 * HW) / 4)                  // 1568
                cpa16(vs + idx * 16u, v4 + idx);
        }
        CP_COMMIT();
    }
    __syncthreads();                  // part complete

    // ============ Phase 2: flat softmax over 2401 ============
    float lmax = -INFINITY;
    for (int p = t; p < HW2; p += NTHR) {
        float sv = part[p] + part[HW2 + p] + part[2 * HW2 + p] + part[3 * HW2 + p];
        att[p] = sv;
        lmax = fmaxf(lmax, sv);
    }
#pragma unroll
    for (int o = 16; o > 0; o >>= 1)
        lmax = fmaxf(lmax, __shfl_xor_sync(0xFFFFFFFFu, lmax, o));
    if ((t & 31) == 0) red[t >> 5] = lmax;
    __syncthreads();
    float bmax = red[0];
#pragma unroll
    for (int w = 1; w < 8; ++w) bmax = fmaxf(bmax, red[w]);

    float lsum = 0.f;
    for (int p = t; p < HW2; p += NTHR) {
        float e = __expf(att[p] - bmax);
        att[p] = e;
        lsum += e;
    }
    __syncthreads();                  // red (max) reads done
#pragma unroll
    for (int o = 16; o > 0; o >>= 1)
        lsum += __shfl_xor_sync(0xFFFFFFFFu, lsum, o);
    if ((t & 31) == 0) red[t >> 5] = lsum;
    __syncthreads();
    float bsum = red[0];
#pragma unroll
    for (int w = 1; w < 8; ++w) bsum += red[w];
    const float inv = 1.f / bsum;
    for (int p = t; p < HW2; p += NTHR) att[p] *= inv;
    // att reads in phase 3 are after the per-pass __syncthreads

    // ============ Phase 3: out = v @ att + v (double-buffered) ============
    float* o_s = part;                // 6272 floats staging

    const int jt    = t & 7;          // active < 7
    const int ctile = t >> 3;         // 0..31 -> 4 rows

    auto load_v = [&](int pass, int stage) {
        const float4* v4 = (const float4*)(vb + pass * CH3 * HW);
        unsigned vs = smem_u + (unsigned)(stage * CH3 * HW) * 4u;
#pragma unroll
        for (int it = 0; it < 7; ++it) {
            int idx = t + it * NTHR;
            if (idx < (CH3 * HW) / 4)
                cpa16(vs + idx * 16u, v4 + idx);
        }
    };

    for (int pass = 0; pass < NCH3; ++pass) {
        const int s = pass & 1;
        if (pass + 1 < NCH3) {
            load_v(pass + 1, s ^ 1);
            CP_COMMIT();
            CP_WAIT1();
        } else {
            CP_WAIT0();
        }
        __syncthreads();              // v(pass) ready; prev STG smem reads done

        const float* v_s = smem + s * CH3 * HW;

        if (jt < 7) {
            float oacc[4][7];
#pragma unroll
            for (int r = 0; r < 4; ++r)
#pragma unroll
                for (int j = 0; j < 7; ++j) oacc[r][j] = 0.f;

            const float* ap = att + jt * 7;
#pragma unroll 2
            for (int i = 0; i < HW; ++i) {
                float av[7];
#pragma unroll
                for (int j = 0; j < 7; ++j) av[j] = ap[i * HW + j];
#pragma unroll
                for (int r = 0; r < 4; ++r) {
                    float vv = v_s[(ctile * 4 + r) * HW + i];
#pragma unroll
                    for (int j = 0; j < 7; ++j)
                        oacc[r][j] += vv * av[j];
                }
            }
#pragma unroll
            for (int r = 0; r < 4; ++r) {
                int c = ctile * 4 + r;
#pragma unroll
                for (int j = 0; j < 7; ++j) {
                    int col = jt * 7 + j;
                    o_s[c * HW + col] = oacc[r][j] + v_s[c * HW + col];
                }
            }
        }
        __syncthreads();              // o_s complete

        float4* od4 = (float4*)(ob + pass * CH3 * HW);
        const float4* os4 = (const float4*)o_s;
#pragma unroll
        for (int it = 0; it < 7; ++it) {
            int idx = t + it * NTHR;
            if (idx < (CH3 * HW) / 4)
                od4[idx] = os4[idx];
        }
        // o_s reuse ordered by next pass's post-wait __syncthreads
    }
}

extern "C" void kernel_launch(void* const* d_in, const int* in_sizes, int n_in,
                              void* d_out, int out_size)
{
    const float* v = (const float*)d_in[0];   // v1
    const float* q = (const float*)d_in[1];   // q1
    const float* k = (const float*)d_in[2];   // k1
    float* out = (float*)d_out;

    const int B = in_sizes[0] / (CCH * HW);
    const size_t smem_bytes = SM_FLOATS * sizeof(float);

    cudaFuncSetAttribute(pam_kernel,
                         cudaFuncAttributeMaxDynamicSharedMemorySize,
                         (int)smem_bytes);
    pam_kernel<<<B, NTHR, smem_bytes>>>(v, q, k, out);
}